// round 2
// baseline (speedup 1.0000x reference)
#include <cuda_runtime.h>
#include <math.h>

// ---------------------------------------------------------------------------
// LlamaCatFlow: 7 midpoint flow steps (14 velocity evals) + VQ argmin.
// B=32, S=256 -> R=8192 rows, D=16, V=8192, TEMP=0.8, n_steps=8.
// velocity(t,x) = (softmax((xW + b + t*tp)/TEMP) @ codebook - x) / (1 - t + eps)
// Design: warp handles ROWB=4 rows (amortizes smem crossbar 4x),
//         packed f32x2 FMA (halves FMA-pipe instruction count).
// ---------------------------------------------------------------------------

#define R_TOTAL 8192
#define DD 16
#define VV 8192
#define VT 256
#define WPB 8                    // warps per block
#define THREADS (WPB * 32)       // 256
#define ROWB 4                   // rows per warp
#define RPB (WPB * ROWB)         // 32 rows per block
#define NBLK (R_TOTAL / RPB)     // 256
#define PAD 20                   // 80B row pitch: 16B-aligned, conflict-free LDS.128

typedef unsigned long long u64;

__device__ __forceinline__ u64 pk2(float lo, float hi) {
    u64 r; asm("mov.b64 %0,{%1,%2};" : "=l"(r) : "f"(lo), "f"(hi)); return r;
}
__device__ __forceinline__ void upk2(u64 a, float& lo, float& hi) {
    asm("mov.b64 {%0,%1},%2;" : "=f"(lo), "=f"(hi) : "l"(a));
}
__device__ __forceinline__ u64 fma2(u64 a, u64 b, u64 c) {
    u64 d; asm("fma.rn.f32x2 %0,%1,%2,%3;" : "=l"(d) : "l"(a), "l"(b), "l"(c)); return d;
}
__device__ __forceinline__ u64 mul2(u64 a, u64 b) {
    u64 d; asm("mul.rn.f32x2 %0,%1,%2;" : "=l"(d) : "l"(a), "l"(b)); return d;
}
__device__ __forceinline__ u64 add2(u64 a, u64 b) {
    u64 d; asm("add.rn.f32x2 %0,%1,%2;" : "=l"(d) : "l"(a), "l"(b)); return d;
}

__device__ __align__(16) float g_x  [R_TOTAL * DD];
__device__ __align__(16) float g_xt [R_TOTAL * DD];
__device__ __align__(16) float g_cn [VV];

// ---------------------------------------------------------------------------
// dst = x_base + scale * (softmax_mu(x_eval) - x_eval),  scale precomputed.
// 1/TEMP folded into smem W tile and bias tile.
// ---------------------------------------------------------------------------
__global__ __launch_bounds__(THREADS, 1)
void vel_kernel(const float* __restrict__ x_eval,
                const float* __restrict__ x_base,
                float* __restrict__ dst,
                float t, float scale,
                const float* __restrict__ Wm,   // [D, V]
                const float* __restrict__ bm,   // [V]
                const float* __restrict__ tpm,  // [V]
                const float* __restrict__ cbm)  // [V, D]
{
    __shared__ __align__(16) float Ws[VT * PAD];
    __shared__ __align__(16) float Cs[VT * PAD];
    __shared__ float Bs[VT];

    const int tid  = threadIdx.x;
    const int wid  = tid >> 5;
    const int lane = tid & 31;
    const int rbase = blockIdx.x * RPB + wid * ROWB;
    const float invT = 1.25f; // 1/0.8

    // each lane holds all ROWB rows' x as 8 packed pairs per row (broadcast LDG)
    u64 xq[ROWB][8];
    #pragma unroll
    for (int r = 0; r < ROWB; ++r) {
        const ulonglong2* xp = (const ulonglong2*)(x_eval + (rbase + r) * DD);
        ulonglong2 q0 = xp[0], q1 = xp[1], q2 = xp[2], q3 = xp[3];
        xq[r][0] = q0.x; xq[r][1] = q0.y; xq[r][2] = q1.x; xq[r][3] = q1.y;
        xq[r][4] = q2.x; xq[r][5] = q2.y; xq[r][6] = q3.x; xq[r][7] = q3.y;
    }

    float m[ROWB], s[ROWB];
    u64 acc[ROWB][8];
    #pragma unroll
    for (int r = 0; r < ROWB; ++r) {
        m[r] = -1e30f; s[r] = 0.f;
        #pragma unroll
        for (int k = 0; k < 8; ++k) acc[r][k] = 0ull;
    }

    for (int tile = 0; tile < VV / VT; ++tile) {
        const int v0 = tile * VT;
        // stage W tile pre-scaled by 1/TEMP: Ws[v*PAD + d]
        #pragma unroll
        for (int k = 0; k < (DD * VT) / THREADS; ++k) {   // 16 iters
            int idx = tid + k * THREADS;
            int d = idx >> 8;           // / VT
            int v = idx & (VT - 1);
            Ws[v * PAD + d] = Wm[d * VV + v0 + v] * invT;
        }
        // stage codebook tile: Cs[v*PAD + d]
        #pragma unroll
        for (int k = 0; k < (DD * VT) / THREADS; ++k) {
            int idx = tid + k * THREADS;
            int v = idx >> 4;
            int d = idx & (DD - 1);
            Cs[v * PAD + d] = cbm[(v0 + v) * DD + d];
        }
        Bs[tid] = (bm[v0 + tid] + t * tpm[v0 + tid]) * invT;
        __syncthreads();

        #pragma unroll
        for (int jj = 0; jj < VT / 32; ++jj) {
            const int j = jj * 32 + lane;
            const ulonglong2* wp = (const ulonglong2*)(Ws + j * PAD);
            ulonglong2 wa = wp[0], wb = wp[1], wc = wp[2], wd = wp[3];
            const float bj = Bs[j];
            const ulonglong2* cp = (const ulonglong2*)(Cs + j * PAD);
            ulonglong2 ca = cp[0], cb = cp[1], cc = cp[2], cd = cp[3];

            #pragma unroll
            for (int r = 0; r < ROWB; ++r) {
                u64 d0 = mul2(xq[r][0], wa.x);
                u64 d1 = mul2(xq[r][1], wa.y);
                u64 d2 = mul2(xq[r][2], wb.x);
                u64 d3 = mul2(xq[r][3], wb.y);
                d0 = fma2(xq[r][4], wc.x, d0);
                d1 = fma2(xq[r][5], wc.y, d1);
                d2 = fma2(xq[r][6], wd.x, d2);
                d3 = fma2(xq[r][7], wd.y, d3);
                d0 = add2(add2(d0, d1), add2(d2, d3));
                float lo, hi; upk2(d0, lo, hi);
                float l = lo + hi + bj;

                if (l > m[r]) {             // rare: rescale running state
                    float c = __expf(m[r] - l);
                    m[r] = l;
                    s[r] *= c;
                    u64 cc2 = pk2(c, c);
                    #pragma unroll
                    for (int k = 0; k < 8; ++k) acc[r][k] = mul2(acc[r][k], cc2);
                }
                float p = __expf(l - m[r]);
                s[r] += p;
                u64 pp = pk2(p, p);
                acc[r][0] = fma2(pp, ca.x, acc[r][0]);
                acc[r][1] = fma2(pp, ca.y, acc[r][1]);
                acc[r][2] = fma2(pp, cb.x, acc[r][2]);
                acc[r][3] = fma2(pp, cb.y, acc[r][3]);
                acc[r][4] = fma2(pp, cc.x, acc[r][4]);
                acc[r][5] = fma2(pp, cc.y, acc[r][5]);
                acc[r][6] = fma2(pp, cd.x, acc[r][6]);
                acc[r][7] = fma2(pp, cd.y, acc[r][7]);
            }
        }
        __syncthreads();
    }

    // per-row warp-wide online-softmax combine + fused integrate/write
    #pragma unroll
    for (int r = 0; r < ROWB; ++r) {
        #pragma unroll
        for (int off = 16; off; off >>= 1) {
            float om = __shfl_xor_sync(0xffffffffu, m[r], off);
            float os = __shfl_xor_sync(0xffffffffu, s[r], off);
            float M  = fmaxf(m[r], om);
            float c1 = __expf(m[r] - M);
            float c2 = __expf(om - M);
            u64 c1p = pk2(c1, c1), c2p = pk2(c2, c2);
            s[r] = s[r] * c1 + os * c2;
            #pragma unroll
            for (int k = 0; k < 8; ++k) {
                u64 oa = __shfl_xor_sync(0xffffffffu, acc[r][k], off);
                acc[r][k] = fma2(oa, c2p, mul2(acc[r][k], c1p));
            }
            m[r] = M;
        }
        float inv = 1.0f / s[r];
        float mu = 0.f;
        #pragma unroll
        for (int k = 0; k < 8; ++k) {
            float lo, hi; upk2(acc[r][k], lo, hi);
            if (lane == 2 * k)     mu = lo;
            if (lane == 2 * k + 1) mu = hi;
        }
        if (lane < DD) {
            int row = rbase + r;
            float xev = x_eval[row * DD + lane];
            float xb  = x_base[row * DD + lane];
            dst[row * DD + lane] = fmaf(scale, mu * inv - xev, xb);
        }
    }
}

// ---------------------------------------------------------------------------
// ||codebook_v||^2 precompute
// ---------------------------------------------------------------------------
__global__ void cnorm_kernel(const float* __restrict__ cbm)
{
    int v = blockIdx.x * blockDim.x + threadIdx.x;
    if (v >= VV) return;
    const float4* cp = (const float4*)(cbm + v * DD);
    float4 c0 = cp[0], c1 = cp[1], c2 = cp[2], c3 = cp[3];
    g_cn[v] = c0.x*c0.x + c0.y*c0.y + c0.z*c0.z + c0.w*c0.w
            + c1.x*c1.x + c1.y*c1.y + c1.z*c1.z + c1.w*c1.w
            + c2.x*c2.x + c2.y*c2.y + c2.z*c2.z + c2.w*c2.w
            + c3.x*c3.x + c3.y*c3.y + c3.z*c3.z + c3.w*c3.w;
}

// ---------------------------------------------------------------------------
// VQ argmin: argmin_v ||c_v||^2 - 2 x.c_v  (first-index tie-break like jnp)
// ---------------------------------------------------------------------------
__global__ __launch_bounds__(THREADS, 1)
void quant_kernel(const float* __restrict__ x,
                  float* __restrict__ out_idx,
                  const float* __restrict__ cbm)
{
    __shared__ __align__(16) float Cs[VT * PAD];
    __shared__ float Ns[VT];

    const int tid  = threadIdx.x;
    const int wid  = tid >> 5;
    const int lane = tid & 31;
    const int rbase = blockIdx.x * RPB + wid * ROWB;

    u64 xq[ROWB][8];
    #pragma unroll
    for (int r = 0; r < ROWB; ++r) {
        const ulonglong2* xp = (const ulonglong2*)(x + (rbase + r) * DD);
        ulonglong2 q0 = xp[0], q1 = xp[1], q2 = xp[2], q3 = xp[3];
        xq[r][0] = q0.x; xq[r][1] = q0.y; xq[r][2] = q1.x; xq[r][3] = q1.y;
        xq[r][4] = q2.x; xq[r][5] = q2.y; xq[r][6] = q3.x; xq[r][7] = q3.y;
    }

    float best[ROWB];
    int   bidx[ROWB];
    #pragma unroll
    for (int r = 0; r < ROWB; ++r) { best[r] = 3.4e38f; bidx[r] = 0; }

    for (int tile = 0; tile < VV / VT; ++tile) {
        const int v0 = tile * VT;
        #pragma unroll
        for (int k = 0; k < (DD * VT) / THREADS; ++k) {
            int idx = tid + k * THREADS;
            int v = idx >> 4;
            int d = idx & (DD - 1);
            Cs[v * PAD + d] = cbm[(v0 + v) * DD + d];
        }
        Ns[tid] = g_cn[v0 + tid];
        __syncthreads();

        #pragma unroll
        for (int jj = 0; jj < VT / 32; ++jj) {
            const int j = jj * 32 + lane;
            const ulonglong2* cp = (const ulonglong2*)(Cs + j * PAD);
            ulonglong2 ca = cp[0], cb = cp[1], cc = cp[2], cd = cp[3];
            const float nsj = Ns[j];
            const int v = v0 + j;
            #pragma unroll
            for (int r = 0; r < ROWB; ++r) {
                u64 d0 = mul2(xq[r][0], ca.x);
                u64 d1 = mul2(xq[r][1], ca.y);
                u64 d2 = mul2(xq[r][2], cb.x);
                u64 d3 = mul2(xq[r][3], cb.y);
                d0 = fma2(xq[r][4], cc.x, d0);
                d1 = fma2(xq[r][5], cc.y, d1);
                d2 = fma2(xq[r][6], cd.x, d2);
                d3 = fma2(xq[r][7], cd.y, d3);
                d0 = add2(add2(d0, d1), add2(d2, d3));
                float lo, hi; upk2(d0, lo, hi);
                float sc = fmaf(-2.0f, lo + hi, nsj);
                if (sc < best[r]) { best[r] = sc; bidx[r] = v; }  // strict <: first
            }
        }
        __syncthreads();
    }

    #pragma unroll
    for (int r = 0; r < ROWB; ++r) {
        float b = best[r]; int bi = bidx[r];
        #pragma unroll
        for (int off = 16; off; off >>= 1) {
            float ob = __shfl_xor_sync(0xffffffffu, b, off);
            int   oi = __shfl_xor_sync(0xffffffffu, bi, off);
            if (ob < b || (ob == b && oi < bi)) { b = ob; bi = oi; }
        }
        if (lane == 0) out_idx[rbase + r] = (float)bi;
    }
}

// ---------------------------------------------------------------------------
__global__ void copy_kernel(const float4* __restrict__ src, float4* __restrict__ dst, int n4)
{
    int i = blockIdx.x * blockDim.x + threadIdx.x;
    if (i < n4) dst[i] = src[i];
}

// ---------------------------------------------------------------------------
extern "C" void kernel_launch(void* const* d_in, const int* in_sizes, int n_in,
                              void* d_out, int out_size)
{
    const float* x0  = (const float*)d_in[0];  // [B,S,D]
    const float* cbm = (const float*)d_in[1];  // [V,D]
    const float* Wm  = (const float*)d_in[2];  // [D,V]
    const float* bm  = (const float*)d_in[3];  // [V]
    const float* tpm = (const float*)d_in[4];  // [V]
    float* out = (float*)d_out;

    float *px = nullptr, *pxt = nullptr;
    cudaGetSymbolAddress((void**)&px,  g_x);
    cudaGetSymbolAddress((void**)&pxt, g_xt);

    const float dt   = 1.0f / 7.0f;     // ts[1]-ts[0], n_steps=8
    const float half = dt * 0.5f;
    const float eps  = 1e-10f;

    const float* cur = x0;
    for (int i = 0; i < 7; ++i) {
        float t1 = (float)i * dt;
        float s1 = half / (1.0f - t1 + eps);
        vel_kernel<<<NBLK, THREADS>>>(cur, cur, pxt, t1, s1, Wm, bm, tpm, cbm);
        float t2 = t1 + half;
        float s2 = dt / (1.0f - t2 + eps);
        vel_kernel<<<NBLK, THREADS>>>(pxt, cur, px, t2, s2, Wm, bm, tpm, cbm);
        cur = px;
    }

    const int XN = R_TOTAL * DD;  // 131072 floats of x_final
    if (out_size >= XN + R_TOTAL) {
        // tuple output: x_final then indices (as float)
        copy_kernel<<<(XN / 4 + 255) / 256, 256>>>((const float4*)px, (float4*)out, XN / 4);
        cnorm_kernel<<<VV / 256, 256>>>(cbm);
        quant_kernel<<<NBLK, THREADS>>>(px, out + XN, cbm);
    } else if (out_size >= XN) {
        copy_kernel<<<(XN / 4 + 255) / 256, 256>>>((const float4*)px, (float4*)out, XN / 4);
    } else {
        cnorm_kernel<<<VV / 256, 256>>>(cbm);
        quant_kernel<<<NBLK, THREADS>>>(px, out, cbm);
    }
}

// round 11
// speedup vs baseline: 1.1240x; 1.1240x over previous
#include <cuda_runtime.h>
#include <math.h>

// ---------------------------------------------------------------------------
// LlamaCatFlow: 7 midpoint flow steps (14 velocity evals) + VQ argmin.
// B=32, S=256 -> R=8192 rows, D=16, V=8192, TEMP=0.8, n_steps=8.
// R10 (== R9 resubmit): ROWB=2, 2 CTA/SM (16 warps), packed f32x2 FMA,
//   branchless deferred-max softmax over 128-v half-tiles (register-safe).
// ---------------------------------------------------------------------------

#define R_TOTAL 8192
#define DD 16
#define VV 8192
#define VT 256
#define WPB 8                    // warps per block
#define THREADS (WPB * 32)       // 256
#define ROWB 2                   // rows per warp
#define RPB (WPB * ROWB)         // 16 rows per block
#define NBLK (R_TOTAL / RPB)     // 512
#define PAD 20                   // 80B pitch: 16B-aligned, conflict-free LDS.128

typedef unsigned long long u64;

__device__ __forceinline__ u64 pk2(float lo, float hi) {
    u64 r; asm("mov.b64 %0,{%1,%2};" : "=l"(r) : "f"(lo), "f"(hi)); return r;
}
__device__ __forceinline__ void upk2(u64 a, float& lo, float& hi) {
    asm("mov.b64 {%0,%1},%2;" : "=f"(lo), "=f"(hi) : "l"(a));
}
__device__ __forceinline__ u64 fma2(u64 a, u64 b, u64 c) {
    u64 d; asm("fma.rn.f32x2 %0,%1,%2,%3;" : "=l"(d) : "l"(a), "l"(b), "l"(c)); return d;
}
__device__ __forceinline__ u64 mul2(u64 a, u64 b) {
    u64 d; asm("mul.rn.f32x2 %0,%1,%2;" : "=l"(d) : "l"(a), "l"(b)); return d;
}
__device__ __forceinline__ u64 add2(u64 a, u64 b) {
    u64 d; asm("add.rn.f32x2 %0,%1,%2;" : "=l"(d) : "l"(a), "l"(b)); return d;
}

__device__ __align__(16) float g_x  [R_TOTAL * DD];
__device__ __align__(16) float g_xt [R_TOTAL * DD];
__device__ __align__(16) float g_cn [VV];

// ---------------------------------------------------------------------------
// dst = x_base + scale * (softmax_mu(x_eval) - x_eval),  scale precomputed.
// 1/TEMP folded into x (per row) and bias tile.
// ---------------------------------------------------------------------------
__global__ __launch_bounds__(THREADS, 2)
void vel_kernel(const float* __restrict__ x_eval,
                const float* __restrict__ x_base,
                float* __restrict__ dst,
                float t, float scale,
                const float* __restrict__ Wm,   // [D, V]
                const float* __restrict__ bm,   // [V]
                const float* __restrict__ tpm,  // [V]
                const float* __restrict__ cbm)  // [V, D]
{
    __shared__ __align__(16) float Ws[VT * PAD];
    __shared__ __align__(16) float Cs[VT * PAD];
    __shared__ float Bs[VT];

    const int tid  = threadIdx.x;
    const int wid  = tid >> 5;
    const int lane = tid & 31;
    const int rbase = blockIdx.x * RPB + wid * ROWB;
    const float invT = 1.25f; // 1/0.8

    // per-warp x rows, pre-scaled by 1/TEMP, as 8 packed f32 pairs per row
    u64 xq[ROWB][8];
    {
        const u64 iv2 = pk2(invT, invT);
        #pragma unroll
        for (int r = 0; r < ROWB; ++r) {
            const ulonglong2* xp = (const ulonglong2*)(x_eval + (rbase + r) * DD);
            ulonglong2 q0 = xp[0], q1 = xp[1], q2 = xp[2], q3 = xp[3];
            xq[r][0] = mul2(q0.x, iv2); xq[r][1] = mul2(q0.y, iv2);
            xq[r][2] = mul2(q1.x, iv2); xq[r][3] = mul2(q1.y, iv2);
            xq[r][4] = mul2(q2.x, iv2); xq[r][5] = mul2(q2.y, iv2);
            xq[r][6] = mul2(q3.x, iv2); xq[r][7] = mul2(q3.y, iv2);
        }
    }

    float m[ROWB], s[ROWB];
    u64 acc[ROWB][8];
    #pragma unroll
    for (int r = 0; r < ROWB; ++r) {
        m[r] = -1e30f; s[r] = 0.f;
        #pragma unroll
        for (int k = 0; k < 8; ++k) acc[r][k] = 0ull;
    }

    for (int tile = 0; tile < VV / VT; ++tile) {
        const int v0 = tile * VT;
        // ---- stage W tile: coalesced LDG.32 per d-row ----
        #pragma unroll
        for (int d = 0; d < DD; ++d) {
            Ws[tid * PAD + d] = Wm[d * VV + v0 + tid];
        }
        // ---- stage C tile: LDG.128 / STS.128 ----
        #pragma unroll
        for (int k = 0; k < 4; ++k) {
            int f = tid + k * THREADS;             // float4 index in [0,1024)
            int v = f >> 2, i = f & 3;
            float4 c4 = ((const float4*)(cbm + (v0 + v) * DD))[i];
            *(float4*)(Cs + v * PAD + 4 * i) = c4;
        }
        Bs[tid] = (bm[v0 + tid] + t * tpm[v0 + tid]) * invT;
        __syncthreads();

        // ---- two 128-v half-tiles: 4-wide logits, deferred max, accumulate ----
        #pragma unroll
        for (int h = 0; h < 2; ++h) {
            float lg[ROWB][4];
            #pragma unroll
            for (int jj = 0; jj < 4; ++jj) {
                const int j = h * 128 + jj * 32 + lane;
                const ulonglong2* wp = (const ulonglong2*)(Ws + j * PAD);
                ulonglong2 wa = wp[0], wb = wp[1], wc = wp[2], wd = wp[3];
                const float bj = Bs[j];
                #pragma unroll
                for (int r = 0; r < ROWB; ++r) {
                    u64 d0 = mul2(xq[r][0], wa.x);
                    u64 d1 = mul2(xq[r][1], wa.y);
                    u64 d2 = mul2(xq[r][2], wb.x);
                    u64 d3 = mul2(xq[r][3], wb.y);
                    d0 = fma2(xq[r][4], wc.x, d0);
                    d1 = fma2(xq[r][5], wc.y, d1);
                    d2 = fma2(xq[r][6], wd.x, d2);
                    d3 = fma2(xq[r][7], wd.y, d3);
                    d0 = add2(add2(d0, d1), add2(d2, d3));
                    float lo, hi; upk2(d0, lo, hi);
                    lg[r][jj] = lo + hi + bj;
                }
            }

            // per-row half-tile max + single branchless rescale
            #pragma unroll
            for (int r = 0; r < ROWB; ++r) {
                float tm = fmaxf(fmaxf(lg[r][0], lg[r][1]), fmaxf(lg[r][2], lg[r][3]));
                float mn = fmaxf(m[r], tm);
                float c  = __expf(m[r] - mn);      // ==1.0 when unchanged
                m[r] = mn;
                s[r] *= c;
                u64 cp = pk2(c, c);
                #pragma unroll
                for (int k = 0; k < 8; ++k) acc[r][k] = mul2(acc[r][k], cp);
            }

            // exps + accumulate (dual partial sums)
            #pragma unroll
            for (int r = 0; r < ROWB; ++r) {
                float s0 = 0.f, s1 = 0.f;
                #pragma unroll
                for (int jj = 0; jj < 4; ++jj) {
                    const int j = h * 128 + jj * 32 + lane;
                    const ulonglong2* cp = (const ulonglong2*)(Cs + j * PAD);
                    ulonglong2 ca = cp[0], cb = cp[1], cc = cp[2], cd = cp[3];
                    float p = __expf(lg[r][jj] - m[r]);
                    if (jj & 1) s1 += p; else s0 += p;
                    u64 pp = pk2(p, p);
                    acc[r][0] = fma2(pp, ca.x, acc[r][0]);
                    acc[r][1] = fma2(pp, ca.y, acc[r][1]);
                    acc[r][2] = fma2(pp, cb.x, acc[r][2]);
                    acc[r][3] = fma2(pp, cb.y, acc[r][3]);
                    acc[r][4] = fma2(pp, cc.x, acc[r][4]);
                    acc[r][5] = fma2(pp, cc.y, acc[r][5]);
                    acc[r][6] = fma2(pp, cd.x, acc[r][6]);
                    acc[r][7] = fma2(pp, cd.y, acc[r][7]);
                }
                s[r] += s0 + s1;
            }
        }
        __syncthreads();
    }

    // per-row warp-wide online-softmax combine + fused integrate/write
    #pragma unroll
    for (int r = 0; r < ROWB; ++r) {
        #pragma unroll
        for (int off = 16; off; off >>= 1) {
            float om = __shfl_xor_sync(0xffffffffu, m[r], off);
            float os = __shfl_xor_sync(0xffffffffu, s[r], off);
            float M  = fmaxf(m[r], om);
            float c1 = __expf(m[r] - M);
            float c2 = __expf(om - M);
            u64 c1p = pk2(c1, c1), c2p = pk2(c2, c2);
            s[r] = s[r] * c1 + os * c2;
            #pragma unroll
            for (int k = 0; k < 8; ++k) {
                u64 oa = __shfl_xor_sync(0xffffffffu, acc[r][k], off);
                acc[r][k] = fma2(oa, c2p, mul2(acc[r][k], c1p));
            }
            m[r] = M;
        }
        float inv = 1.0f / s[r];
        float mu = 0.f;
        #pragma unroll
        for (int k = 0; k < 8; ++k) {
            float lo, hi; upk2(acc[r][k], lo, hi);
            if (lane == 2 * k)     mu = lo;
            if (lane == 2 * k + 1) mu = hi;
        }
        if (lane < DD) {
            int row = rbase + r;
            float xev = x_eval[row * DD + lane];
            float xb  = x_base[row * DD + lane];
            dst[row * DD + lane] = fmaf(scale, mu * inv - xev, xb);
        }
    }
}

// ---------------------------------------------------------------------------
// ||codebook_v||^2 precompute
// ---------------------------------------------------------------------------
__global__ void cnorm_kernel(const float* __restrict__ cbm)
{
    int v = blockIdx.x * blockDim.x + threadIdx.x;
    if (v >= VV) return;
    const float4* cp = (const float4*)(cbm + v * DD);
    float4 c0 = cp[0], c1 = cp[1], c2 = cp[2], c3 = cp[3];
    g_cn[v] = c0.x*c0.x + c0.y*c0.y + c0.z*c0.z + c0.w*c0.w
            + c1.x*c1.x + c1.y*c1.y + c1.z*c1.z + c1.w*c1.w
            + c2.x*c2.x + c2.y*c2.y + c2.z*c2.z + c2.w*c2.w
            + c3.x*c3.x + c3.y*c3.y + c3.z*c3.z + c3.w*c3.w;
}

// ---------------------------------------------------------------------------
// VQ argmin: argmin_v ||c_v||^2 - 2 x.c_v  (first-index tie-break like jnp)
// ---------------------------------------------------------------------------
__global__ __launch_bounds__(THREADS, 2)
void quant_kernel(const float* __restrict__ x,
                  float* __restrict__ out_idx,
                  const float* __restrict__ cbm)
{
    __shared__ __align__(16) float Cs[VT * PAD];
    __shared__ float Ns[VT];

    const int tid  = threadIdx.x;
    const int wid  = tid >> 5;
    const int lane = tid & 31;
    const int rbase = blockIdx.x * RPB + wid * ROWB;

    u64 xq[ROWB][8];
    #pragma unroll
    for (int r = 0; r < ROWB; ++r) {
        const ulonglong2* xp = (const ulonglong2*)(x + (rbase + r) * DD);
        ulonglong2 q0 = xp[0], q1 = xp[1], q2 = xp[2], q3 = xp[3];
        xq[r][0] = q0.x; xq[r][1] = q0.y; xq[r][2] = q1.x; xq[r][3] = q1.y;
        xq[r][4] = q2.x; xq[r][5] = q2.y; xq[r][6] = q3.x; xq[r][7] = q3.y;
    }

    float best[ROWB];
    int   bidx[ROWB];
    #pragma unroll
    for (int r = 0; r < ROWB; ++r) { best[r] = 3.4e38f; bidx[r] = 0; }

    for (int tile = 0; tile < VV / VT; ++tile) {
        const int v0 = tile * VT;
        #pragma unroll
        for (int k = 0; k < 4; ++k) {
            int f = tid + k * THREADS;
            int v = f >> 2, i = f & 3;
            float4 c4 = ((const float4*)(cbm + (v0 + v) * DD))[i];
            *(float4*)(Cs + v * PAD + 4 * i) = c4;
        }
        Ns[tid] = g_cn[v0 + tid];
        __syncthreads();

        #pragma unroll
        for (int jj = 0; jj < VT / 32; ++jj) {
            const int j = jj * 32 + lane;
            const ulonglong2* cp = (const ulonglong2*)(Cs + j * PAD);
            ulonglong2 ca = cp[0], cb = cp[1], cc = cp[2], cd = cp[3];
            const float nsj = Ns[j];
            const int v = v0 + j;
            #pragma unroll
            for (int r = 0; r < ROWB; ++r) {
                u64 d0 = mul2(xq[r][0], ca.x);
                u64 d1 = mul2(xq[r][1], ca.y);
                u64 d2 = mul2(xq[r][2], cb.x);
                u64 d3 = mul2(xq[r][3], cb.y);
                d0 = fma2(xq[r][4], cc.x, d0);
                d1 = fma2(xq[r][5], cc.y, d1);
                d2 = fma2(xq[r][6], cd.x, d2);
                d3 = fma2(xq[r][7], cd.y, d3);
                d0 = add2(add2(d0, d1), add2(d2, d3));
                float lo, hi; upk2(d0, lo, hi);
                float sc = fmaf(-2.0f, lo + hi, nsj);
                if (sc < best[r]) { best[r] = sc; bidx[r] = v; }  // strict <: first
            }
        }
        __syncthreads();
    }

    #pragma unroll
    for (int r = 0; r < ROWB; ++r) {
        float b = best[r]; int bi = bidx[r];
        #pragma unroll
        for (int off = 16; off; off >>= 1) {
            float ob = __shfl_xor_sync(0xffffffffu, b, off);
            int   oi = __shfl_xor_sync(0xffffffffu, bi, off);
            if (ob < b || (ob == b && oi < bi)) { b = ob; bi = oi; }
        }
        if (lane == 0) out_idx[rbase + r] = (float)bi;
    }
}

// ---------------------------------------------------------------------------
__global__ void copy_kernel(const float4* __restrict__ src, float4* __restrict__ dst, int n4)
{
    int i = blockIdx.x * blockDim.x + threadIdx.x;
    if (i < n4) dst[i] = src[i];
}

// ---------------------------------------------------------------------------
extern "C" void kernel_launch(void* const* d_in, const int* in_sizes, int n_in,
                              void* d_out, int out_size)
{
    const float* x0  = (const float*)d_in[0];  // [B,S,D]
    const float* cbm = (const float*)d_in[1];  // [V,D]
    const float* Wm  = (const float*)d_in[2];  // [D,V]
    const float* bm  = (const float*)d_in[3];  // [V]
    const float* tpm = (const float*)d_in[4];  // [V]
    float* out = (float*)d_out;

    float *px = nullptr, *pxt = nullptr;
    cudaGetSymbolAddress((void**)&px,  g_x);
    cudaGetSymbolAddress((void**)&pxt, g_xt);

    const float dt   = 1.0f / 7.0f;     // ts[1]-ts[0], n_steps=8
    const float half = dt * 0.5f;
    const float eps  = 1e-10f;

    const float* cur = x0;
    for (int i = 0; i < 7; ++i) {
        float t1 = (float)i * dt;
        float s1 = half / (1.0f - t1 + eps);
        vel_kernel<<<NBLK, THREADS>>>(cur, cur, pxt, t1, s1, Wm, bm, tpm, cbm);
        float t2 = t1 + half;
        float s2 = dt / (1.0f - t2 + eps);
        vel_kernel<<<NBLK, THREADS>>>(pxt, cur, px, t2, s2, Wm, bm, tpm, cbm);
        cur = px;
    }

    const int XN = R_TOTAL * DD;  // 131072 floats of x_final
    if (out_size >= XN + R_TOTAL) {
        // tuple output: x_final then indices (as float)
        copy_kernel<<<(XN / 4 + 255) / 256, 256>>>((const float4*)px, (float4*)out, XN / 4);
        cnorm_kernel<<<VV / 256, 256>>>(cbm);
        quant_kernel<<<NBLK, THREADS>>>(px, out + XN, cbm);
    } else if (out_size >= XN) {
        copy_kernel<<<(XN / 4 + 255) / 256, 256>>>((const float4*)px, (float4*)out, XN / 4);
    } else {
        cnorm_kernel<<<VV / 256, 256>>>(cbm);
        quant_kernel<<<NBLK, THREADS>>>(px, out, cbm);
    }
}

// round 13
// speedup vs baseline: 1.3276x; 1.1812x over previous
#include <cuda_runtime.h>
#include <math.h>

// ---------------------------------------------------------------------------
// LlamaCatFlow: 7 midpoint flow steps (14 velocity evals) + VQ argmin.
// B=32, S=256 -> R=8192 rows, D=16, V=8192, TEMP=0.8, n_steps=8.
// R13 (== R12 resubmit): BROADCAST mapping. Lane <-> row (32 rows/CTA, x in
//   registers), v broadcast from smem (N=1 -> ~16x less crossbar traffic).
//   8 warps split V per tile; per-warp online-softmax partials combined in
//   smem. W pre-transposed+prescaled by wtrans kernel. Packed f32x2 FMA.
// ---------------------------------------------------------------------------

#define R_TOTAL 8192
#define DD 16
#define VV 8192

typedef unsigned long long u64;

__device__ __forceinline__ u64 pk2(float lo, float hi) {
    u64 r; asm("mov.b64 %0,{%1,%2};" : "=l"(r) : "f"(lo), "f"(hi)); return r;
}
__device__ __forceinline__ void upk2(u64 a, float& lo, float& hi) {
    asm("mov.b64 {%0,%1},%2;" : "=f"(lo), "=f"(hi) : "l"(a));
}
__device__ __forceinline__ u64 fma2(u64 a, u64 b, u64 c) {
    u64 d; asm("fma.rn.f32x2 %0,%1,%2,%3;" : "=l"(d) : "l"(a), "l"(b), "l"(c)); return d;
}
__device__ __forceinline__ u64 mul2(u64 a, u64 b) {
    u64 d; asm("mul.rn.f32x2 %0,%1,%2;" : "=l"(d) : "l"(a), "l"(b)); return d;
}
__device__ __forceinline__ u64 add2(u64 a, u64 b) {
    u64 d; asm("add.rn.f32x2 %0,%1,%2;" : "=l"(d) : "l"(a), "l"(b)); return d;
}

__device__ __align__(16) float g_x  [R_TOTAL * DD];
__device__ __align__(16) float g_xt [R_TOTAL * DD];
__device__ __align__(16) float g_cn [VV];
__device__ __align__(16) float g_wt [VV * DD];   // W^T prescaled by 1/TEMP

// ---------------------------------------------------------------------------
// W transpose + 1/TEMP prefold: g_wt[v][d] = Wm[d][v] * invT
// ---------------------------------------------------------------------------
__global__ void wtrans_kernel(const float* __restrict__ Wm)
{
    int v = blockIdx.x * blockDim.x + threadIdx.x;
    if (v >= VV) return;
    #pragma unroll
    for (int d = 0; d < DD; ++d)
        g_wt[v * DD + d] = Wm[d * VV + v] * 1.25f;
}

// ---------------------------------------------------------------------------
// vel: dst = x_base + scale * (softmax_mu(x_eval) - x_eval)
// CTA = 32 rows (lane l of every warp owns row R0+l). Per 256-v tile staged
// in smem, warp w consumes slice [w*32,(w+1)*32) via BROADCAST reads.
// ---------------------------------------------------------------------------
#define VWPB 8
#define VTHREADS 256
#define VROWS 32
#define VNBLK (R_TOTAL / VROWS)   // 256
#define VT 256

__global__ __launch_bounds__(VTHREADS, 2)
void vel_kernel(const float* __restrict__ x_eval,
                const float* __restrict__ x_base,
                float* __restrict__ dst,
                float t, float scale,
                const float* __restrict__ bm,   // [V]
                const float* __restrict__ tpm,  // [V]
                const float* __restrict__ cbm)  // [V, D]
{
    // Ws[256*16] | Cs[256*16] | Bs[256]; combine area aliases Ws/Cs.
    __shared__ __align__(16) float SM[VT * DD * 2 + VT];
    float* Ws = SM;
    float* Cs = SM + VT * DD;
    float* Bs = SM + VT * DD * 2;

    const int tid  = threadIdx.x;
    const int wid  = tid >> 5;
    const int lane = tid & 31;
    const int R0   = blockIdx.x * VROWS;
    const int row  = R0 + lane;

    // lane's x row (unscaled; invT folded into g_wt and Bs)
    u64 xq[8];
    {
        const ulonglong2* xp = (const ulonglong2*)(x_eval + row * DD);
        ulonglong2 q0 = xp[0], q1 = xp[1], q2 = xp[2], q3 = xp[3];
        xq[0]=q0.x; xq[1]=q0.y; xq[2]=q1.x; xq[3]=q1.y;
        xq[4]=q2.x; xq[5]=q2.y; xq[6]=q3.x; xq[7]=q3.y;
    }

    float m = -1e30f, s = 0.f;
    u64 acc[8];
    #pragma unroll
    for (int k = 0; k < 8; ++k) acc[k] = 0ull;

    for (int tile = 0; tile < VV / VT; ++tile) {
        const int v0 = tile * VT;
        // stage W^T tile: 1024 float4, 4 per thread (LDG.128/STS.128)
        #pragma unroll
        for (int k = 0; k < 4; ++k) {
            int f = tid + k * VTHREADS;
            ((float4*)Ws)[f] = ((const float4*)(g_wt + v0 * DD))[f];
        }
        // stage C tile
        #pragma unroll
        for (int k = 0; k < 4; ++k) {
            int f = tid + k * VTHREADS;
            ((float4*)Cs)[f] = ((const float4*)(cbm + v0 * DD))[f];
        }
        Bs[tid] = (bm[v0 + tid] + t * tpm[v0 + tid]) * 1.25f;
        __syncthreads();

        // warp's 32-v slice, in 4 chunks of 8 (deferred max per chunk)
        #pragma unroll
        for (int c = 0; c < 4; ++c) {
            const int vb = wid * 32 + c * 8;
            float lg[8];
            #pragma unroll
            for (int e = 0; e < 8; ++e) {
                const ulonglong2* wp = (const ulonglong2*)(Ws + (vb + e) * DD);
                ulonglong2 wa = wp[0], wb2 = wp[1], wc = wp[2], wd = wp[3];
                u64 d0 = mul2(xq[0], wa.x);
                u64 d1 = mul2(xq[1], wa.y);
                u64 d2 = mul2(xq[2], wb2.x);
                u64 d3 = mul2(xq[3], wb2.y);
                d0 = fma2(xq[4], wc.x, d0);
                d1 = fma2(xq[5], wc.y, d1);
                d2 = fma2(xq[6], wd.x, d2);
                d3 = fma2(xq[7], wd.y, d3);
                d0 = add2(add2(d0, d1), add2(d2, d3));
                float lo, hi; upk2(d0, lo, hi);
                lg[e] = lo + hi + Bs[vb + e];
            }
            // chunk max + single branchless rescale
            float t0 = fmaxf(lg[0], lg[1]);
            float t1 = fmaxf(lg[2], lg[3]);
            float t2 = fmaxf(lg[4], lg[5]);
            float t3 = fmaxf(lg[6], lg[7]);
            float mn = fmaxf(m, fmaxf(fmaxf(t0, t1), fmaxf(t2, t3)));
            float cf = __expf(m - mn);     // ==1 when unchanged
            m = mn;
            s *= cf;
            u64 cfp = pk2(cf, cf);
            #pragma unroll
            for (int k = 0; k < 8; ++k) acc[k] = mul2(acc[k], cfp);
            // exps + accumulate
            float s0 = 0.f, s1 = 0.f;
            #pragma unroll
            for (int e = 0; e < 8; ++e) {
                const ulonglong2* cp = (const ulonglong2*)(Cs + (vb + e) * DD);
                ulonglong2 ca = cp[0], cb = cp[1], cc = cp[2], cd = cp[3];
                float p = __expf(lg[e] - m);
                if (e & 1) s1 += p; else s0 += p;
                u64 pp = pk2(p, p);
                acc[0] = fma2(pp, ca.x, acc[0]);
                acc[1] = fma2(pp, ca.y, acc[1]);
                acc[2] = fma2(pp, cb.x, acc[2]);
                acc[3] = fma2(pp, cb.y, acc[3]);
                acc[4] = fma2(pp, cc.x, acc[4]);
                acc[5] = fma2(pp, cc.y, acc[5]);
                acc[6] = fma2(pp, cd.x, acc[6]);
                acc[7] = fma2(pp, cd.y, acc[7]);
            }
            s += s0 + s1;
        }
        __syncthreads();
    }

    // ---- combine 8 per-warp partials per row (smem, pitch 20 floats) ----
    // layout per (warp p, lane l): base (p*32+l)*20 : [m, s, -, -, acc16]
    {
        float* cmb = SM;                       // reuse Ws/Cs area (5120 floats)
        float* pb = cmb + (wid * 32 + lane) * 20;
        pb[0] = m; pb[1] = s;
        ulonglong2* ap = (ulonglong2*)(pb + 4);
        ap[0] = make_ulonglong2(acc[0], acc[1]);
        ap[1] = make_ulonglong2(acc[2], acc[3]);
        ap[2] = make_ulonglong2(acc[4], acc[5]);
        ap[3] = make_ulonglong2(acc[6], acc[7]);
    }
    __syncthreads();

    if (wid == 0) {
        const float* cmb = SM;
        // global max over 8 partials for this row
        float M = -1e30f;
        #pragma unroll
        for (int p = 0; p < 8; ++p)
            M = fmaxf(M, cmb[(p * 32 + lane) * 20]);
        float st = 0.f;
        u64 at[8];
        #pragma unroll
        for (int k = 0; k < 8; ++k) at[k] = 0ull;
        #pragma unroll
        for (int p = 0; p < 8; ++p) {
            const float* pb = cmb + (p * 32 + lane) * 20;
            float cf = __expf(pb[0] - M);
            st = fmaf(pb[1], cf, st);
            u64 cfp = pk2(cf, cf);
            const ulonglong2* ap = (const ulonglong2*)(pb + 4);
            ulonglong2 a0 = ap[0], a1 = ap[1], a2 = ap[2], a3 = ap[3];
            at[0] = fma2(a0.x, cfp, at[0]);
            at[1] = fma2(a0.y, cfp, at[1]);
            at[2] = fma2(a1.x, cfp, at[2]);
            at[3] = fma2(a1.y, cfp, at[3]);
            at[4] = fma2(a2.x, cfp, at[4]);
            at[5] = fma2(a2.y, cfp, at[5]);
            at[6] = fma2(a3.x, cfp, at[6]);
            at[7] = fma2(a3.y, cfp, at[7]);
        }
        float inv = 1.0f / st;
        // integrate + write: dst = xb + scale*(mu - xe)
        const float* xe = x_eval + row * DD;
        const float* xb = x_base + row * DD;
        float4 o[4];
        #pragma unroll
        for (int k = 0; k < 8; ++k) {
            float lo, hi; upk2(at[k], lo, hi);
            float mu0 = lo * inv, mu1 = hi * inv;
            ((float*)o)[2 * k]     = fmaf(scale, mu0 - xe[2 * k],     xb[2 * k]);
            ((float*)o)[2 * k + 1] = fmaf(scale, mu1 - xe[2 * k + 1], xb[2 * k + 1]);
        }
        float4* dp = (float4*)(dst + row * DD);
        dp[0] = o[0]; dp[1] = o[1]; dp[2] = o[2]; dp[3] = o[3];
    }
}

// ---------------------------------------------------------------------------
// ||codebook_v||^2 precompute
// ---------------------------------------------------------------------------
__global__ void cnorm_kernel(const float* __restrict__ cbm)
{
    int v = blockIdx.x * blockDim.x + threadIdx.x;
    if (v >= VV) return;
    const float4* cp = (const float4*)(cbm + v * DD);
    float4 c0 = cp[0], c1 = cp[1], c2 = cp[2], c3 = cp[3];
    g_cn[v] = c0.x*c0.x + c0.y*c0.y + c0.z*c0.z + c0.w*c0.w
            + c1.x*c1.x + c1.y*c1.y + c1.z*c1.z + c1.w*c1.w
            + c2.x*c2.x + c2.y*c2.y + c2.z*c2.z + c2.w*c2.w
            + c3.x*c3.x + c3.y*c3.y + c3.z*c3.z + c3.w*c3.w;
}

// ---------------------------------------------------------------------------
// VQ argmin (kept from R9 — measured cheap): argmin ||c||^2 - 2 x.c
// ---------------------------------------------------------------------------
#define QWPB 8
#define QTHREADS 256
#define QROWB 2
#define QRPB (QWPB * QROWB)
#define QNBLK (R_TOTAL / QRPB)
#define QPAD 20

__global__ __launch_bounds__(QTHREADS, 2)
void quant_kernel(const float* __restrict__ x,
                  float* __restrict__ out_idx,
                  const float* __restrict__ cbm)
{
    __shared__ __align__(16) float Cs[VT * QPAD];
    __shared__ float Ns[VT];

    const int tid  = threadIdx.x;
    const int wid  = tid >> 5;
    const int lane = tid & 31;
    const int rbase = blockIdx.x * QRPB + wid * QROWB;

    u64 xq[QROWB][8];
    #pragma unroll
    for (int r = 0; r < QROWB; ++r) {
        const ulonglong2* xp = (const ulonglong2*)(x + (rbase + r) * DD);
        ulonglong2 q0 = xp[0], q1 = xp[1], q2 = xp[2], q3 = xp[3];
        xq[r][0] = q0.x; xq[r][1] = q0.y; xq[r][2] = q1.x; xq[r][3] = q1.y;
        xq[r][4] = q2.x; xq[r][5] = q2.y; xq[r][6] = q3.x; xq[r][7] = q3.y;
    }

    float best[QROWB];
    int   bidx[QROWB];
    #pragma unroll
    for (int r = 0; r < QROWB; ++r) { best[r] = 3.4e38f; bidx[r] = 0; }

    for (int tile = 0; tile < VV / VT; ++tile) {
        const int v0 = tile * VT;
        #pragma unroll
        for (int k = 0; k < 4; ++k) {
            int f = tid + k * QTHREADS;
            int v = f >> 2, i = f & 3;
            float4 c4 = ((const float4*)(cbm + (v0 + v) * DD))[i];
            *(float4*)(Cs + v * QPAD + 4 * i) = c4;
        }
        Ns[tid] = g_cn[v0 + tid];
        __syncthreads();

        #pragma unroll
        for (int jj = 0; jj < VT / 32; ++jj) {
            const int j = jj * 32 + lane;
            const ulonglong2* cp = (const ulonglong2*)(Cs + j * QPAD);
            ulonglong2 ca = cp[0], cb = cp[1], cc = cp[2], cd = cp[3];
            const float nsj = Ns[j];
            const int v = v0 + j;
            #pragma unroll
            for (int r = 0; r < QROWB; ++r) {
                u64 d0 = mul2(xq[r][0], ca.x);
                u64 d1 = mul2(xq[r][1], ca.y);
                u64 d2 = mul2(xq[r][2], cb.x);
                u64 d3 = mul2(xq[r][3], cb.y);
                d0 = fma2(xq[r][4], cc.x, d0);
                d1 = fma2(xq[r][5], cc.y, d1);
                d2 = fma2(xq[r][6], cd.x, d2);
                d3 = fma2(xq[r][7], cd.y, d3);
                d0 = add2(add2(d0, d1), add2(d2, d3));
                float lo, hi; upk2(d0, lo, hi);
                float sc = fmaf(-2.0f, lo + hi, nsj);
                if (sc < best[r]) { best[r] = sc; bidx[r] = v; }  // strict <: first
            }
        }
        __syncthreads();
    }

    #pragma unroll
    for (int r = 0; r < QROWB; ++r) {
        float b = best[r]; int bi = bidx[r];
        #pragma unroll
        for (int off = 16; off; off >>= 1) {
            float ob = __shfl_xor_sync(0xffffffffu, b, off);
            int   oi = __shfl_xor_sync(0xffffffffu, bi, off);
            if (ob < b || (ob == b && oi < bi)) { b = ob; bi = oi; }
        }
        if (lane == 0) out_idx[rbase + r] = (float)bi;
    }
}

// ---------------------------------------------------------------------------
__global__ void copy_kernel(const float4* __restrict__ src, float4* __restrict__ dst, int n4)
{
    int i = blockIdx.x * blockDim.x + threadIdx.x;
    if (i < n4) dst[i] = src[i];
}

// ---------------------------------------------------------------------------
extern "C" void kernel_launch(void* const* d_in, const int* in_sizes, int n_in,
                              void* d_out, int out_size)
{
    const float* x0  = (const float*)d_in[0];  // [B,S,D]
    const float* cbm = (const float*)d_in[1];  // [V,D]
    const float* Wm  = (const float*)d_in[2];  // [D,V]
    const float* bm  = (const float*)d_in[3];  // [V]
    const float* tpm = (const float*)d_in[4];  // [V]
    float* out = (float*)d_out;

    float *px = nullptr, *pxt = nullptr;
    cudaGetSymbolAddress((void**)&px,  g_x);
    cudaGetSymbolAddress((void**)&pxt, g_xt);

    const float dt   = 1.0f / 7.0f;     // ts[1]-ts[0], n_steps=8
    const float half = dt * 0.5f;
    const float eps  = 1e-10f;

    wtrans_kernel<<<VV / 256, 256>>>(Wm);

    const float* cur = x0;
    for (int i = 0; i < 7; ++i) {
        float t1 = (float)i * dt;
        float s1 = half / (1.0f - t1 + eps);
        vel_kernel<<<VNBLK, VTHREADS>>>(cur, cur, pxt, t1, s1, bm, tpm, cbm);
        float t2 = t1 + half;
        float s2 = dt / (1.0f - t2 + eps);
        vel_kernel<<<VNBLK, VTHREADS>>>(pxt, cur, px, t2, s2, bm, tpm, cbm);
        cur = px;
    }

    const int XN = R_TOTAL * DD;  // 131072 floats of x_final
    if (out_size >= XN + R_TOTAL) {
        // tuple output: x_final then indices (as float)
        copy_kernel<<<(XN / 4 + 255) / 256, 256>>>((const float4*)px, (float4*)out, XN / 4);
        cnorm_kernel<<<VV / 256, 256>>>(cbm);
        quant_kernel<<<QNBLK, QTHREADS>>>(px, out + XN, cbm);
    } else if (out_size >= XN) {
        copy_kernel<<<(XN / 4 + 255) / 256, 256>>>((const float4*)px, (float4*)out, XN / 4);
    } else {
        cnorm_kernel<<<VV / 256, 256>>>(cbm);
        quant_kernel<<<QNBLK, QTHREADS>>>(px, out, cbm);
    }
}